// round 4
// baseline (speedup 1.0000x reference)
#include <cuda_runtime.h>
#include <cuda_bf16.h>
#include <math.h>

// Problem constants (fixed by setup_inputs)
#define SPEC 512
#define OUTN 4096
#define INN  4096

// ---------------------------------------------------------------------------
// Scratch (no allocation allowed -> __device__ globals)
// ---------------------------------------------------------------------------
__device__ float g_V[SPEC * OUTN];     // V[s,o] = pos*cpos + neg*cneg  (8 MB)
__device__ float g_cpos[OUTN];
__device__ float g_cneg[OUTN];
__device__ float g_bpos[OUTN];
__device__ float g_bneg[OUTN];
__device__ float g_factor[OUTN];       // (1-alpha) for unstable neurons, else 0

// ---------------------------------------------------------------------------
// Phase 0: per-output-neuron scalar coefficients.
//
// Reference decomposition: for each o the contribution to uA_out[s,i] is
//   pos[s,o]*P[o,i] + neg[s,o]*N[o,i]
// where (except for the unstable simplex-upper term, handled by residual_k):
//   P[o,i] = cpos[o]*W[o,i],  N[o,i] = cneg[o]*W[o,i]
// and ubias picks up bpos/bneg per o.
// ---------------------------------------------------------------------------
__global__ void scalars_k(const float* __restrict__ bias,
                          const float* __restrict__ lb_in,
                          const float* __restrict__ ub_in,
                          const float* __restrict__ alpha)
{
    int o = blockIdx.x * blockDim.x + threadIdx.x;
    if (o >= OUTN) return;

    float b  = bias[o];
    float lb = lb_in[o];
    float ub = ub_in[o];
    float a  = alpha[o];       // alpha shape (1, OUT, 1) -> flat [OUT]
    float oma = 1.0f - a;

    float lo_d = (fabsf(lb) >= fabsf(ub)) ? 1.0f : 0.0f;

    // simplex / branch part (scalar pieces only; unstable upper handled by residual)
    float upc_s, loc_s, upb, lob, fac;
    if (ub <= 0.0f) {
        upc_s = 0.0f; loc_s = 0.0f; upb = 0.0f; lob = 0.0f; fac = 0.0f;
    } else if (lb >= 0.0f) {
        upc_s = 1.0f; loc_s = 1.0f; upb = b;    lob = b;    fac = 0.0f;
    } else {
        upc_s = 0.0f;              // non-scalar simplex coeff -> residual kernel
        loc_s = lo_d;
        upb   = fmaxf(b, 0.0f);
        lob   = lo_d * b;
        fac   = oma;
    }

    // CROWN relaxation part
    float lb_r = fminf(lb, 0.0f);
    float ub_r = fmaxf(ub, 0.0f);
    ub_r = fmaxf(ub_r, lb_r + 1e-8f);
    float ud  = ub_r / (ub_r - lb_r);
    float upB = -lb_r * ud;
    float ldd = (ud > 0.5f) ? 1.0f : 0.0f;

    g_cpos[o]   = oma * upc_s + ud * a;
    g_cneg[o]   = oma * loc_s + ldd * a;
    g_bpos[o]   = oma * upb + upB + ud * a * b;
    g_bneg[o]   = oma * lob + ldd * a * b;
    g_factor[o] = fac;
}

// ---------------------------------------------------------------------------
// Phase 1: V[s,o] = relu(uA)*cpos + min(uA,0)*cneg, fused with the ubias
// reduction: ubias[s] = sum_o pos*bpos + neg*bneg. One block per s.
// ---------------------------------------------------------------------------
__global__ __launch_bounds__(256) void vbias_k(const float* __restrict__ uA,
                                               float* __restrict__ ubias)
{
    int s = blockIdx.x;
    const float* row  = uA  + (size_t)s * OUTN;
    float*       vrow = g_V + (size_t)s * OUTN;

    float acc = 0.0f;
    for (int o = threadIdx.x; o < OUTN; o += 256) {
        float u = row[o];
        float p = fmaxf(u, 0.0f);
        float n = fminf(u, 0.0f);
        vrow[o] = p * g_cpos[o] + n * g_cneg[o];
        acc += p * g_bpos[o] + n * g_bneg[o];
    }

    __shared__ float sred[256];
    sred[threadIdx.x] = acc;
    __syncthreads();
    #pragma unroll
    for (int st = 128; st > 0; st >>= 1) {
        if (threadIdx.x < st) sred[threadIdx.x] += sred[threadIdx.x + st];
        __syncthreads();
    }
    if (threadIdx.x == 0) ubias[s] = sred[0];
}

// ---------------------------------------------------------------------------
// Phase 2: SGEMM  C[s,i] = sum_o V[s,o] * W[o,i]
// M=512, N=4096, K=4096, all fp32. 128x128 block tile, BK=16, 8x8 per thread.
// ---------------------------------------------------------------------------
__global__ __launch_bounds__(256) void sgemm_k(const float* __restrict__ B,
                                               float* __restrict__ C)
{
    const int M = SPEC, N = INN, K = OUTN;
    const float* A = g_V;   // [M, K]

    __shared__ float As[16][128];
    __shared__ float Bs[16][128];

    int bm = blockIdx.y * 128;
    int bn = blockIdx.x * 128;
    int tid = threadIdx.x;
    int tx = tid & 15;        // 0..15 -> column group
    int ty = tid >> 4;        // 0..15 -> row group

    float acc[8][8] = {};
    float ar[8], br[8];

    for (int k0 = 0; k0 < K; k0 += 16) {
        // A tile: 128 rows x 16 cols = 512 float4 loads, 2 per thread (transposed store)
        #pragma unroll
        for (int i = 0; i < 2; i++) {
            int idx = tid + i * 256;          // 0..511
            int row = idx >> 2;
            int c4  = (idx & 3) * 4;
            float4 v = *reinterpret_cast<const float4*>(&A[(size_t)(bm + row) * K + k0 + c4]);
            As[c4 + 0][row] = v.x;
            As[c4 + 1][row] = v.y;
            As[c4 + 2][row] = v.z;
            As[c4 + 3][row] = v.w;
        }
        // B tile: 16 rows x 128 cols
        #pragma unroll
        for (int i = 0; i < 2; i++) {
            int idx = tid + i * 256;
            int row = idx >> 5;
            int c4  = (idx & 31) * 4;
            *reinterpret_cast<float4*>(&Bs[row][c4]) =
                *reinterpret_cast<const float4*>(&B[(size_t)(k0 + row) * N + bn + c4]);
        }
        __syncthreads();

        #pragma unroll
        for (int k = 0; k < 16; k++) {
            #pragma unroll
            for (int i = 0; i < 8; i++) ar[i] = As[k][ty * 8 + i];
            #pragma unroll
            for (int j = 0; j < 8; j++) br[j] = Bs[k][tx * 8 + j];
            #pragma unroll
            for (int i = 0; i < 8; i++)
                #pragma unroll
                for (int j = 0; j < 8; j++)
                    acc[i][j] = fmaf(ar[i], br[j], acc[i][j]);
        }
        __syncthreads();
    }

    #pragma unroll
    for (int i = 0; i < 8; i++) {
        size_t r = (size_t)(bm + ty * 8 + i) * N + bn + tx * 8;
        #pragma unroll
        for (int j = 0; j < 8; j += 4) {
            float4 v = make_float4(acc[i][j], acc[i][j + 1], acc[i][j + 2], acc[i][j + 3]);
            *reinterpret_cast<float4*>(&C[r + j]) = v;
        }
    }
}

// ---------------------------------------------------------------------------
// Phase 3: non-scalar simplex residual for unstable neurons with alpha != 1:
//   out[s,i] += pos[s,o] * (1-a[o]) * (relu(W[o,i]+b[o]) - relu(b[o]))
// With the bench inputs alpha == 1 so every factor is 0 -> every block exits
// after one load. Kept for mathematical generality.
// ---------------------------------------------------------------------------
__global__ void residual_k(const float* __restrict__ uA,
                           const float* __restrict__ W,
                           const float* __restrict__ bias,
                           float* __restrict__ out)
{
    int o = blockIdx.x;
    float f = g_factor[o];
    if (f == 0.0f) return;

    float b  = bias[o];
    float rb = fmaxf(b, 0.0f);
    for (int s = 0; s < SPEC; s++) {
        float p = fmaxf(uA[(size_t)s * OUTN + o], 0.0f);
        float coef = p * f;
        if (coef == 0.0f) continue;
        for (int i = threadIdx.x; i < INN; i += blockDim.x) {
            float sc = fmaxf(W[(size_t)o * INN + i] + b, 0.0f) - rb;
            atomicAdd(&out[(size_t)s * INN + i], coef * sc);
        }
    }
}

// ---------------------------------------------------------------------------
// Launch. Input order (metadata): last_uA, weight, bias, preact_lb, preact_ub, alpha.
// Output: uA [512*4096] then ubias [512], fp32, concatenated.
// ---------------------------------------------------------------------------
extern "C" void kernel_launch(void* const* d_in, const int* in_sizes, int n_in,
                              void* d_out, int out_size)
{
    const float* uA    = (const float*)d_in[0];
    const float* W     = (const float*)d_in[1];
    const float* bias  = (const float*)d_in[2];
    const float* lb    = (const float*)d_in[3];
    const float* ub    = (const float*)d_in[4];
    const float* alpha = (const float*)d_in[5];

    float* out_uA   = (float*)d_out;
    float* out_bias = out_uA + (size_t)SPEC * INN;

    scalars_k<<<OUTN / 256, 256>>>(bias, lb, ub, alpha);
    vbias_k<<<SPEC, 256>>>(uA, out_bias);
    sgemm_k<<<dim3(INN / 128, SPEC / 128), 256>>>(W, out_uA);
    residual_k<<<OUTN, 128>>>(uA, W, bias, out_uA);
}

// round 9
// speedup vs baseline: 2.1655x; 2.1655x over previous
#include <cuda_runtime.h>
#include <cuda_bf16.h>
#include <math.h>
#include <stdint.h>

#define SPEC 512
#define OUTN 4096
#define INN  4096

// ---------------------------------------------------------------------------
// Scratch (__device__ globals; no allocation allowed)
// ---------------------------------------------------------------------------
__device__ float g_cpos[OUTN];
__device__ float g_cneg[OUTN];
__device__ float g_bpos[OUTN];
__device__ float g_bneg[OUTN];
__device__ float g_factor[OUTN];
__device__ __nv_bfloat16 g_Vhi[SPEC * OUTN];          // A operand, [s, o] K-major
__device__ __nv_bfloat16 g_Vlo[SPEC * OUTN];
__device__ __nv_bfloat16 g_Wthi[(size_t)INN * OUTN];  // B operand, [i, o] K-major
__device__ __nv_bfloat16 g_Wtlo[(size_t)INN * OUTN];

// ---------------------------------------------------------------------------
// PTX helpers (sm_80+ only — compute_103 virtual arch safe)
// ---------------------------------------------------------------------------
__device__ __forceinline__ uint32_t smem_u32(const void* p) {
    uint32_t a;
    asm("{ .reg .u64 t; cvta.to.shared.u64 t, %1; cvt.u32.u64 %0, t; }" : "=r"(a) : "l"(p));
    return a;
}
__device__ __forceinline__ void cp16(uint32_t dst, const void* src) {
    asm volatile("cp.async.cg.shared.global [%0], [%1], 16;" :: "r"(dst), "l"(src));
}
#define CP_COMMIT() asm volatile("cp.async.commit_group;" ::: "memory")
#define CP_WAIT2()  asm volatile("cp.async.wait_group 2;" ::: "memory")
#define CP_WAIT1()  asm volatile("cp.async.wait_group 1;" ::: "memory")
#define CP_WAIT0()  asm volatile("cp.async.wait_group 0;" ::: "memory")

__device__ __forceinline__ void ldm_x4(uint32_t* r, uint32_t addr) {
    asm volatile("ldmatrix.sync.aligned.m8n8.x4.shared.b16 {%0,%1,%2,%3}, [%4];"
        : "=r"(r[0]), "=r"(r[1]), "=r"(r[2]), "=r"(r[3]) : "r"(addr));
}
__device__ __forceinline__ void ldm_x2(uint32_t* r, uint32_t addr) {
    asm volatile("ldmatrix.sync.aligned.m8n8.x2.shared.b16 {%0,%1}, [%2];"
        : "=r"(r[0]), "=r"(r[1]) : "r"(addr));
}
__device__ __forceinline__ void mma_bf16(float* c, const uint32_t* a, const uint32_t* b) {
    asm volatile("mma.sync.aligned.m16n8k16.row.col.f32.bf16.bf16.f32 "
        "{%0,%1,%2,%3}, {%4,%5,%6,%7}, {%8,%9}, {%0,%1,%2,%3};"
        : "+f"(c[0]), "+f"(c[1]), "+f"(c[2]), "+f"(c[3])
        : "r"(a[0]), "r"(a[1]), "r"(a[2]), "r"(a[3]), "r"(b[0]), "r"(b[1]));
}

// ---------------------------------------------------------------------------
// Phase 0: per-output-neuron scalar coefficients (unchanged math)
// ---------------------------------------------------------------------------
__global__ void scalars_k(const float* __restrict__ bias,
                          const float* __restrict__ lb_in,
                          const float* __restrict__ ub_in,
                          const float* __restrict__ alpha)
{
    int o = blockIdx.x * blockDim.x + threadIdx.x;
    if (o >= OUTN) return;

    float b  = bias[o];
    float lb = lb_in[o];
    float ub = ub_in[o];
    float a  = alpha[o];
    float oma = 1.0f - a;

    float lo_d = (fabsf(lb) >= fabsf(ub)) ? 1.0f : 0.0f;

    float upc_s, loc_s, upb, lob, fac;
    if (ub <= 0.0f) {
        upc_s = 0.0f; loc_s = 0.0f; upb = 0.0f; lob = 0.0f; fac = 0.0f;
    } else if (lb >= 0.0f) {
        upc_s = 1.0f; loc_s = 1.0f; upb = b;    lob = b;    fac = 0.0f;
    } else {
        upc_s = 0.0f;
        loc_s = lo_d;
        upb   = fmaxf(b, 0.0f);
        lob   = lo_d * b;
        fac   = oma;
    }

    float lb_r = fminf(lb, 0.0f);
    float ub_r = fmaxf(ub, 0.0f);
    ub_r = fmaxf(ub_r, lb_r + 1e-8f);
    float ud  = ub_r / (ub_r - lb_r);
    float upB = -lb_r * ud;
    float ldd = (ud > 0.5f) ? 1.0f : 0.0f;

    g_cpos[o]   = oma * upc_s + ud * a;
    g_cneg[o]   = oma * loc_s + ldd * a;
    g_bpos[o]   = oma * upb + upB + ud * a * b;
    g_bneg[o]   = oma * lob + ldd * a * b;
    g_factor[o] = fac;
}

// ---------------------------------------------------------------------------
// Phase 1: V = pos*cpos + neg*cneg, split into bf16 hi/lo; fused ubias.
// ---------------------------------------------------------------------------
__global__ __launch_bounds__(256) void vbias_k(const float* __restrict__ uA,
                                               float* __restrict__ ubias)
{
    int s = blockIdx.x;
    const float* row = uA + (size_t)s * OUTN;
    __nv_bfloat16* vh = g_Vhi + (size_t)s * OUTN;
    __nv_bfloat16* vl = g_Vlo + (size_t)s * OUTN;

    float acc = 0.0f;
    for (int o = threadIdx.x; o < OUTN; o += 256) {
        float u = row[o];
        float p = fmaxf(u, 0.0f);
        float n = fminf(u, 0.0f);
        float v = p * g_cpos[o] + n * g_cneg[o];
        __nv_bfloat16 hi = __float2bfloat16(v);
        vh[o] = hi;
        vl[o] = __float2bfloat16(v - __bfloat162float(hi));
        acc += p * g_bpos[o] + n * g_bneg[o];
    }

    __shared__ float sred[256];
    sred[threadIdx.x] = acc;
    __syncthreads();
    #pragma unroll
    for (int st = 128; st > 0; st >>= 1) {
        if (threadIdx.x < st) sred[threadIdx.x] += sred[threadIdx.x + st];
        __syncthreads();
    }
    if (threadIdx.x == 0) ubias[s] = sred[0];
}

// ---------------------------------------------------------------------------
// Phase 1b: W transpose + bf16 hi/lo split:  Wt[i,o] = W[o,i]
// ---------------------------------------------------------------------------
__global__ __launch_bounds__(256) void wconv_k(const float* __restrict__ W)
{
    __shared__ float t[32][33];
    int i0 = blockIdx.x * 32, o0 = blockIdx.y * 32;
    int tx = threadIdx.x & 31, ty = threadIdx.x >> 5;   // 32 x 8

    #pragma unroll
    for (int r = 0; r < 4; ++r)
        t[ty + 8 * r][tx] = W[(size_t)(o0 + ty + 8 * r) * INN + i0 + tx];
    __syncthreads();
    #pragma unroll
    for (int r = 0; r < 4; ++r) {
        float v = t[tx][ty + 8 * r];                    // = W[o0+tx][i0+ty+8r]
        size_t idx = (size_t)(i0 + ty + 8 * r) * OUTN + o0 + tx;
        __nv_bfloat16 hi = __float2bfloat16(v);
        g_Wthi[idx] = hi;
        g_Wtlo[idx] = __float2bfloat16(v - __bfloat162float(hi));
    }
}

// ---------------------------------------------------------------------------
// Phase 2: HMMA GEMM  C[s,i] = sum_o V[s,o] * Wt[i,o]
// 3-term bf16 split via mma.sync m16n8k16, fp32 accum in registers.
// 128x128 tile, BK=32, 3-stage cp.async pipeline, 8 warps (2x4 -> 64x32 each).
// ---------------------------------------------------------------------------
#define BK       32
#define NCHUNK   (OUTN / BK)            // 128
#define TROW_B   80                     // 64B data + 16B pad (conflict-free ldmatrix)
#define TILE_SM  (128 * TROW_B)         // 10240 B
#define STAGE_SM (4 * TILE_SM)          // Ahi, Alo, Bhi, Blo = 40960 B
#define GEMM_SMEM (3 * STAGE_SM)        // 122880 B

__global__ __launch_bounds__(256, 1) void gemm_k(float* __restrict__ C)
{
    extern __shared__ char smem[];
    const uint32_t sbase = smem_u32(smem);

    const int tid = threadIdx.x;
    const int wid = tid >> 5;
    const int lid = tid & 31;
    const int bm = blockIdx.y * 128;
    const int bn = blockIdx.x * 128;
    const int wm = wid & 1;             // 2 warps in M (64 rows each)
    const int wn = wid >> 1;            // 4 warps in N (32 cols each)

    const __nv_bfloat16* srcs[4] = {
        g_Vhi  + (size_t)bm * OUTN,
        g_Vlo  + (size_t)bm * OUTN,
        g_Wthi + (size_t)bn * OUTN,
        g_Wtlo + (size_t)bn * OUTN
    };

    // per-thread ldmatrix base offsets (bytes, within a tile)
    const uint32_t aoff = (uint32_t)((wm * 64 + (lid & 15)) * TROW_B + (lid >> 4) * 16);
    const uint32_t boff = (uint32_t)((wn * 32 + (lid & 7)) * TROW_B + ((lid >> 3) & 1) * 16);

    auto load_chunk = [&](int chunk, int st) {
        uint32_t stage = sbase + st * STAGE_SM;
        int k0 = chunk * BK;
        #pragma unroll
        for (int T = 0; T < 4; ++T) {
            const __nv_bfloat16* g = srcs[T] + k0;
            #pragma unroll
            for (int i = 0; i < 2; ++i) {
                int u = tid + i * 256;          // 0..511
                int row = u >> 2;               // 0..127
                int c16 = u & 3;                // 16B unit within 64B row
                cp16(stage + T * TILE_SM + (uint32_t)(row * TROW_B + c16 * 16),
                     g + (size_t)row * OUTN + c16 * 8);
            }
        }
        CP_COMMIT();
    };

    float acc[4][4][4] = {};

    load_chunk(0, 0);
    load_chunk(1, 1);

    for (int c = 0; c < NCHUNK; ++c) {
        if (c + 2 < NCHUNK) { load_chunk(c + 2, (c + 2) % 3); CP_WAIT2(); }
        else if (c + 1 < NCHUNK) { CP_WAIT1(); }
        else { CP_WAIT0(); }
        __syncthreads();

        uint32_t stA = sbase + (c % 3) * STAGE_SM;
        uint32_t stB = stA + 2 * TILE_SM;

        #pragma unroll
        for (int ks = 0; ks < 2; ++ks) {
            uint32_t ah[4][4], al[4][4], bh[4][2], bl[4][2];
            #pragma unroll
            for (int mt = 0; mt < 4; ++mt) {
                uint32_t a = stA + mt * (16 * TROW_B) + ks * 32 + aoff;
                ldm_x4(ah[mt], a);
                ldm_x4(al[mt], a + TILE_SM);
            }
            #pragma unroll
            for (int nt = 0; nt < 4; ++nt) {
                uint32_t b = stB + nt * (8 * TROW_B) + ks * 32 + boff;
                ldm_x2(bh[nt], b);
                ldm_x2(bl[nt], b + TILE_SM);
            }
            #pragma unroll
            for (int mt = 0; mt < 4; ++mt)
                #pragma unroll
                for (int nt = 0; nt < 4; ++nt) {
                    mma_bf16(acc[mt][nt], ah[mt], bh[nt]);
                    mma_bf16(acc[mt][nt], ah[mt], bl[nt]);
                    mma_bf16(acc[mt][nt], al[mt], bh[nt]);
                }
        }
        __syncthreads();
    }

    // epilogue: fragment -> gmem (float2 stores)
    const int r0 = bm + wm * 64 + (lid >> 2);
    const int c0 = bn + wn * 32 + (lid & 3) * 2;
    #pragma unroll
    for (int mt = 0; mt < 4; ++mt) {
        #pragma unroll
        for (int nt = 0; nt < 4; ++nt) {
            int row = r0 + mt * 16;
            int col = c0 + nt * 8;
            *reinterpret_cast<float2*>(&C[(size_t)row * INN + col]) =
                make_float2(acc[mt][nt][0], acc[mt][nt][1]);
            *reinterpret_cast<float2*>(&C[(size_t)(row + 8) * INN + col]) =
                make_float2(acc[mt][nt][2], acc[mt][nt][3]);
        }
    }
}

// ---------------------------------------------------------------------------
// Phase 3: simplex residual for unstable neurons with alpha != 1 (zero here).
// ---------------------------------------------------------------------------
__global__ void residual_k(const float* __restrict__ uA,
                           const float* __restrict__ W,
                           const float* __restrict__ bias,
                           float* __restrict__ out)
{
    for (int o = blockIdx.x; o < OUTN; o += gridDim.x) {
        float f = g_factor[o];
        if (f == 0.0f) continue;

        float b  = bias[o];
        float rb = fmaxf(b, 0.0f);
        for (int s = 0; s < SPEC; s++) {
            float p = fmaxf(uA[(size_t)s * OUTN + o], 0.0f);
            float coef = p * f;
            if (coef == 0.0f) continue;
            for (int i = threadIdx.x; i < INN; i += blockDim.x) {
                float sc = fmaxf(W[(size_t)o * INN + i] + b, 0.0f) - rb;
                atomicAdd(&out[(size_t)s * INN + i], coef * sc);
            }
        }
    }
}

// ---------------------------------------------------------------------------
// Launch
// ---------------------------------------------------------------------------
extern "C" void kernel_launch(void* const* d_in, const int* in_sizes, int n_in,
                              void* d_out, int out_size)
{
    const float* uA    = (const float*)d_in[0];
    const float* W     = (const float*)d_in[1];
    const float* bias  = (const float*)d_in[2];
    const float* lb    = (const float*)d_in[3];
    const float* ub    = (const float*)d_in[4];
    const float* alpha = (const float*)d_in[5];

    float* out_uA   = (float*)d_out;
    float* out_bias = out_uA + (size_t)SPEC * INN;

    static bool attr_done = false;
    if (!attr_done) {
        cudaFuncSetAttribute(gemm_k, cudaFuncAttributeMaxDynamicSharedMemorySize, GEMM_SMEM);
        attr_done = true;
    }

    scalars_k<<<OUTN / 256, 256>>>(bias, lb, ub, alpha);
    wconv_k<<<dim3(INN / 32, OUTN / 32), 256>>>(W);
    vbias_k<<<SPEC, 256>>>(uA, out_bias);
    gemm_k<<<dim3(INN / 128, SPEC / 128), 256, GEMM_SMEM>>>(out_uA);
    residual_k<<<64, 128>>>(uA, W, bias, out_uA);
}

// round 11
// speedup vs baseline: 2.3101x; 1.0668x over previous
#include <cuda_runtime.h>
#include <cuda_bf16.h>
#include <math.h>
#include <stdint.h>

#define SPEC 512
#define OUTN 4096
#define INN  4096

// ---------------------------------------------------------------------------
// Scratch (__device__ globals; no allocation allowed)
// ---------------------------------------------------------------------------
__device__ float g_cpos[OUTN];
__device__ float g_cneg[OUTN];
__device__ float g_bpos[OUTN];
__device__ float g_bneg[OUTN];
__device__ float g_factor[OUTN];
__device__ __align__(16) __nv_bfloat16 g_Vhi[SPEC * OUTN];         // [s][o] row-major
__device__ __align__(16) __nv_bfloat16 g_Vlo[SPEC * OUTN];
__device__ __align__(16) __nv_bfloat16 g_Whi[(size_t)OUTN * INN];  // [o][i] row-major (same as W)
__device__ __align__(16) __nv_bfloat16 g_Wlo[(size_t)OUTN * INN];

// ---------------------------------------------------------------------------
// PTX helpers (sm_80+ only — compute_103 virtual arch safe)
// ---------------------------------------------------------------------------
__device__ __forceinline__ uint32_t smem_u32(const void* p) {
    uint32_t a;
    asm("{ .reg .u64 t; cvta.to.shared.u64 t, %1; cvt.u32.u64 %0, t; }" : "=r"(a) : "l"(p));
    return a;
}
__device__ __forceinline__ void cp16(uint32_t dst, const void* src) {
    asm volatile("cp.async.cg.shared.global [%0], [%1], 16;" :: "r"(dst), "l"(src));
}
#define CP_COMMIT() asm volatile("cp.async.commit_group;" ::: "memory")
#define CP_WAIT2()  asm volatile("cp.async.wait_group 2;" ::: "memory")
#define CP_WAIT1()  asm volatile("cp.async.wait_group 1;" ::: "memory")
#define CP_WAIT0()  asm volatile("cp.async.wait_group 0;" ::: "memory")

__device__ __forceinline__ void ldm_x4(uint32_t* r, uint32_t addr) {
    asm volatile("ldmatrix.sync.aligned.m8n8.x4.shared.b16 {%0,%1,%2,%3}, [%4];"
        : "=r"(r[0]), "=r"(r[1]), "=r"(r[2]), "=r"(r[3]) : "r"(addr));
}
__device__ __forceinline__ void ldm_x4_t(uint32_t* r, uint32_t addr) {
    asm volatile("ldmatrix.sync.aligned.m8n8.x4.trans.shared.b16 {%0,%1,%2,%3}, [%4];"
        : "=r"(r[0]), "=r"(r[1]), "=r"(r[2]), "=r"(r[3]) : "r"(addr));
}
__device__ __forceinline__ void mma_bf16(float* c, const uint32_t* a, const uint32_t* b) {
    asm volatile("mma.sync.aligned.m16n8k16.row.col.f32.bf16.bf16.f32 "
        "{%0,%1,%2,%3}, {%4,%5,%6,%7}, {%8,%9}, {%0,%1,%2,%3};"
        : "+f"(c[0]), "+f"(c[1]), "+f"(c[2]), "+f"(c[3])
        : "r"(a[0]), "r"(a[1]), "r"(a[2]), "r"(a[3]), "r"(b[0]), "r"(b[1]));
}

// ---------------------------------------------------------------------------
// Phase 0: per-output-neuron scalar coefficients (unchanged math)
// ---------------------------------------------------------------------------
__global__ void scalars_k(const float* __restrict__ bias,
                          const float* __restrict__ lb_in,
                          const float* __restrict__ ub_in,
                          const float* __restrict__ alpha)
{
    int o = blockIdx.x * blockDim.x + threadIdx.x;
    if (o >= OUTN) return;

    float b  = bias[o];
    float lb = lb_in[o];
    float ub = ub_in[o];
    float a  = alpha[o];
    float oma = 1.0f - a;

    float lo_d = (fabsf(lb) >= fabsf(ub)) ? 1.0f : 0.0f;

    float upc_s, loc_s, upb, lob, fac;
    if (ub <= 0.0f) {
        upc_s = 0.0f; loc_s = 0.0f; upb = 0.0f; lob = 0.0f; fac = 0.0f;
    } else if (lb >= 0.0f) {
        upc_s = 1.0f; loc_s = 1.0f; upb = b;    lob = b;    fac = 0.0f;
    } else {
        upc_s = 0.0f;
        loc_s = lo_d;
        upb   = fmaxf(b, 0.0f);
        lob   = lo_d * b;
        fac   = oma;
    }

    float lb_r = fminf(lb, 0.0f);
    float ub_r = fmaxf(ub, 0.0f);
    ub_r = fmaxf(ub_r, lb_r + 1e-8f);
    float ud  = ub_r / (ub_r - lb_r);
    float upB = -lb_r * ud;
    float ldd = (ud > 0.5f) ? 1.0f : 0.0f;

    g_cpos[o]   = oma * upc_s + ud * a;
    g_cneg[o]   = oma * loc_s + ldd * a;
    g_bpos[o]   = oma * upb + upB + ud * a * b;
    g_bneg[o]   = oma * lob + ldd * a * b;
    g_factor[o] = fac;
}

// ---------------------------------------------------------------------------
// Phase 1: V = pos*cpos + neg*cneg, split into bf16 hi/lo; fused ubias.
// ---------------------------------------------------------------------------
__global__ __launch_bounds__(256) void vbias_k(const float* __restrict__ uA,
                                               float* __restrict__ ubias)
{
    int s = blockIdx.x;
    const float* row = uA + (size_t)s * OUTN;
    __nv_bfloat16* vh = g_Vhi + (size_t)s * OUTN;
    __nv_bfloat16* vl = g_Vlo + (size_t)s * OUTN;

    float acc = 0.0f;
    for (int o = threadIdx.x; o < OUTN; o += 256) {
        float u = row[o];
        float p = fmaxf(u, 0.0f);
        float n = fminf(u, 0.0f);
        float v = p * g_cpos[o] + n * g_cneg[o];
        __nv_bfloat16 hi = __float2bfloat16(v);
        vh[o] = hi;
        vl[o] = __float2bfloat16(v - __bfloat162float(hi));
        acc += p * g_bpos[o] + n * g_bneg[o];
    }

    __shared__ float sred[256];
    sred[threadIdx.x] = acc;
    __syncthreads();
    #pragma unroll
    for (int st = 128; st > 0; st >>= 1) {
        if (threadIdx.x < st) sred[threadIdx.x] += sred[threadIdx.x + st];
        __syncthreads();
    }
    if (threadIdx.x == 0) ubias[s] = sred[0];
}

// ---------------------------------------------------------------------------
// Phase 1b: pure elementwise W -> bf16 hi/lo split (no transpose needed:
// W[o][i] is already [k][n] row-major for mma row.col + ldmatrix.trans).
// ---------------------------------------------------------------------------
__global__ __launch_bounds__(256) void wsplit_k(const float4* __restrict__ W4)
{
    size_t idx = (size_t)blockIdx.x * 256 + threadIdx.x;   // one float4 each
    float4 v = W4[idx];

    __nv_bfloat16 h0 = __float2bfloat16(v.x);
    __nv_bfloat16 h1 = __float2bfloat16(v.y);
    __nv_bfloat16 h2 = __float2bfloat16(v.z);
    __nv_bfloat16 h3 = __float2bfloat16(v.w);

    __nv_bfloat162 hA, hB, lA, lB;
    hA.x = h0; hA.y = h1; hB.x = h2; hB.y = h3;
    lA.x = __float2bfloat16(v.x - __bfloat162float(h0));
    lA.y = __float2bfloat16(v.y - __bfloat162float(h1));
    lB.x = __float2bfloat16(v.z - __bfloat162float(h2));
    lB.y = __float2bfloat16(v.w - __bfloat162float(h3));

    uint2 hv, lv;
    hv.x = *reinterpret_cast<uint32_t*>(&hA);
    hv.y = *reinterpret_cast<uint32_t*>(&hB);
    lv.x = *reinterpret_cast<uint32_t*>(&lA);
    lv.y = *reinterpret_cast<uint32_t*>(&lB);
    reinterpret_cast<uint2*>(g_Whi)[idx] = hv;
    reinterpret_cast<uint2*>(g_Wlo)[idx] = lv;
}

// ---------------------------------------------------------------------------
// Phase 2: HMMA GEMM  C[s,i] = sum_o V[s,o] * W[o,i]
// 3-term bf16 split via mma.sync m16n8k16, fp32 accum.
// 128x128 CTA tile, BK=32, 3-stage cp.async pipeline, 16 warps (4x4, 32x32 each).
// A = V [s][k] (ldmatrix), B = W [k][n] (ldmatrix.trans).
// ---------------------------------------------------------------------------
#define BK       32
#define NCHUNK   (OUTN / BK)            // 128
#define A_ROW_B  80                     // 64B data + 16B pad
#define A_TILE   (128 * A_ROW_B)        // 10240 B
#define B_ROW_B  272                    // 256B data + 16B pad
#define B_TILE   (32 * B_ROW_B)         // 8704 B
#define STAGE_SM (2 * A_TILE + 2 * B_TILE)   // 37888 B
#define GEMM_SMEM (3 * STAGE_SM)             // 113664 B

__global__ __launch_bounds__(512, 1) void gemm_k(float* __restrict__ C)
{
    extern __shared__ char smem[];
    const uint32_t sbase = smem_u32(smem);

    const int tid = threadIdx.x;
    const int wid = tid >> 5;
    const int lid = tid & 31;
    const int bm = blockIdx.y * 128;
    const int bn = blockIdx.x * 128;
    const int wm = wid & 3;             // 4 warps in M (32 rows each)
    const int wn = wid >> 2;            // 4 warps in N (32 cols each)

    const __nv_bfloat16* srcAh = g_Vhi + (size_t)bm * OUTN;
    const __nv_bfloat16* srcAl = g_Vlo + (size_t)bm * OUTN;
    const __nv_bfloat16* srcBh = g_Whi + bn;
    const __nv_bfloat16* srcBl = g_Wlo + bn;

    // ldmatrix base offsets (bytes within an operand tile)
    // A (non-trans, m16k16): lanes 0-15 rows m, lanes 16-31 same rows @k+8
    const uint32_t aoff = (uint32_t)((wm * 32 + (lid & 15)) * A_ROW_B + (lid >> 4) * 16);
    // B (x4.trans, [k][n]): lanes 0-15 rows k, lane>>4 selects n+8 group
    const uint32_t boff = (uint32_t)((lid & 15) * B_ROW_B + wn * 64 + (lid >> 4) * 16);

    auto load_chunk = [&](int chunk, int st) {
        uint32_t stage = sbase + st * STAGE_SM;
        int k0 = chunk * BK;
        {   // A hi / lo : 128 rows x 4 x 16B each = 512 cp16 per operand
            int row = tid >> 2, u = tid & 3;
            uint32_t d = stage + (uint32_t)(row * A_ROW_B + u * 16);
            const __nv_bfloat16* sh = srcAh + (size_t)row * OUTN + k0 + u * 8;
            const __nv_bfloat16* sl = srcAl + (size_t)row * OUTN + k0 + u * 8;
            cp16(d, sh);
            cp16(d + A_TILE, sl);
        }
        {   // B hi / lo : 32 rows x 16 x 16B each = 512 cp16 per operand
            int row = tid >> 4, u = tid & 15;
            uint32_t d = stage + 2 * A_TILE + (uint32_t)(row * B_ROW_B + u * 16);
            const __nv_bfloat16* sh = srcBh + (size_t)(k0 + row) * INN + u * 8;
            const __nv_bfloat16* sl = srcBl + (size_t)(k0 + row) * INN + u * 8;
            cp16(d, sh);
            cp16(d + B_TILE, sl);
        }
        CP_COMMIT();
    };

    float acc[2][4][4] = {};

    load_chunk(0, 0);
    load_chunk(1, 1);

    for (int c = 0; c < NCHUNK; ++c) {
        if (c + 2 < NCHUNK) { load_chunk(c + 2, (c + 2) % 3); CP_WAIT2(); }
        else if (c + 1 < NCHUNK) { CP_WAIT1(); }
        else { CP_WAIT0(); }
        __syncthreads();

        uint32_t stg = sbase + (c % 3) * STAGE_SM;
        uint32_t aHi = stg, aLo = stg + A_TILE;
        uint32_t bHi = stg + 2 * A_TILE, bLo = bHi + B_TILE;

        #pragma unroll
        for (int ks = 0; ks < 2; ++ks) {
            uint32_t ah[2][4], al[2][4], bh[2][4], bl[2][4];
            #pragma unroll
            for (int mt = 0; mt < 2; ++mt) {
                uint32_t a = (uint32_t)(mt * 16 * A_ROW_B + ks * 32) + aoff;
                ldm_x4(ah[mt], aHi + a);
                ldm_x4(al[mt], aLo + a);
            }
            #pragma unroll
            for (int p = 0; p < 2; ++p) {
                uint32_t b = (uint32_t)(ks * 16 * B_ROW_B + p * 32) + boff;
                ldm_x4_t(bh[p], bHi + b);
                ldm_x4_t(bl[p], bLo + b);
            }
            #pragma unroll
            for (int mt = 0; mt < 2; ++mt)
                #pragma unroll
                for (int nt = 0; nt < 4; ++nt) {
                    const uint32_t* BH = &bh[nt >> 1][(nt & 1) * 2];
                    const uint32_t* BL = &bl[nt >> 1][(nt & 1) * 2];
                    mma_bf16(acc[mt][nt], ah[mt], BH);
                    mma_bf16(acc[mt][nt], ah[mt], BL);
                    mma_bf16(acc[mt][nt], al[mt], BH);
                }
        }
        __syncthreads();
    }

    // epilogue: fragment -> gmem (float2 stores)
    const int r0 = bm + wm * 32 + (lid >> 2);
    const int c0 = bn + wn * 32 + (lid & 3) * 2;
    #pragma unroll
    for (int mt = 0; mt < 2; ++mt) {
        #pragma unroll
        for (int nt = 0; nt < 4; ++nt) {
            int row = r0 + mt * 16;
            int col = c0 + nt * 8;
            *reinterpret_cast<float2*>(&C[(size_t)row * INN + col]) =
                make_float2(acc[mt][nt][0], acc[mt][nt][1]);
            *reinterpret_cast<float2*>(&C[(size_t)(row + 8) * INN + col]) =
                make_float2(acc[mt][nt][2], acc[mt][nt][3]);
        }
    }
}

// ---------------------------------------------------------------------------
// Phase 3: simplex residual for unstable neurons with alpha != 1 (zero here).
// ---------------------------------------------------------------------------
__global__ void residual_k(const float* __restrict__ uA,
                           const float* __restrict__ W,
                           const float* __restrict__ bias,
                           float* __restrict__ out)
{
    for (int o = blockIdx.x; o < OUTN; o += gridDim.x) {
        float f = g_factor[o];
        if (f == 0.0f) continue;

        float b  = bias[o];
        float rb = fmaxf(b, 0.0f);
        for (int s = 0; s < SPEC; s++) {
            float p = fmaxf(uA[(size_t)s * OUTN + o], 0.0f);
            float coef = p * f;
            if (coef == 0.0f) continue;
            for (int i = threadIdx.x; i < INN; i += blockDim.x) {
                float sc = fmaxf(W[(size_t)o * INN + i] + b, 0.0f) - rb;
                atomicAdd(&out[(size_t)s * INN + i], coef * sc);
            }
        }
    }
}

// ---------------------------------------------------------------------------
// Launch
// ---------------------------------------------------------------------------
extern "C" void kernel_launch(void* const* d_in, const int* in_sizes, int n_in,
                              void* d_out, int out_size)
{
    const float* uA    = (const float*)d_in[0];
    const float* W     = (const float*)d_in[1];
    const float* bias  = (const float*)d_in[2];
    const float* lb    = (const float*)d_in[3];
    const float* ub    = (const float*)d_in[4];
    const float* alpha = (const float*)d_in[5];

    float* out_uA   = (float*)d_out;
    float* out_bias = out_uA + (size_t)SPEC * INN;

    static bool attr_done = false;
    if (!attr_done) {
        cudaFuncSetAttribute(gemm_k, cudaFuncAttributeMaxDynamicSharedMemorySize, GEMM_SMEM);
        attr_done = true;
    }

    scalars_k<<<OUTN / 256, 256>>>(bias, lb, ub, alpha);
    wsplit_k<<<(OUTN * (INN / 4)) / 256, 256>>>((const float4*)W);
    vbias_k<<<SPEC, 256>>>(uA, out_bias);
    gemm_k<<<dim3(INN / 128, SPEC / 128), 512, GEMM_SMEM>>>(out_uA);
    residual_k<<<64, 128>>>(uA, W, bias, out_uA);
}